// round 16
// baseline (speedup 1.0000x reference)
#include <cuda_runtime.h>
#include <cuda_bf16.h>
#include <stdint.h>

// Linear causal attention, chunked states, bf16-split mma.sync.
//   O_c = Q_c @ S_c + (tril ⊙ Q_c K_c^T) @ V_c,  S_c = sum_{c'<c} K_{c'}^T V_{c'}
// fp32 GEMM = Ah*Bh + Ah*Bl + Al*Bh in bf16, fp32 accum. Operands natural [t][d];
// transposed fragments via ldmatrix.trans. Causal structure exploited.
// kernC: P GEMM runs FIRST (S cp.async hides under convert+P), V prefetch
// hides under the full-length O1 GEMM; warp->tile map is an SMSP-balanced LUT.

#define NCHUNK 1024
#define CE     16384
#define IMRB   272             // bytes per full image row (136 bf16)
#define IMU4   2176            // uint4 per 128-row full image
#define HPRB   144             // bytes per half image row (72 bf16)

__device__ float g_M[(size_t)NCHUNK * CE];        // K^T V per chunk, fp32
__device__ uint4 g_SH[(size_t)NCHUNK * IMU4];     // exclusive-prefix S, split images
__device__ uint4 g_SL[(size_t)NCHUNK * IMU4];

// ---------------- helpers ----------------
__device__ __forceinline__ uint32_t smem_u32(const void* p) {
    uint32_t a;
    asm("{ .reg .u64 t; cvta.to.shared.u64 t, %1; cvt.u32.u64 %0, t; }" : "=r"(a) : "l"(p));
    return a;
}
__device__ __forceinline__ void ldsm4(uint32_t a, uint32_t* r) {
    asm volatile("ldmatrix.sync.aligned.m8n8.x4.shared.b16 {%0,%1,%2,%3}, [%4];"
                 : "=r"(r[0]), "=r"(r[1]), "=r"(r[2]), "=r"(r[3]) : "r"(a));
}
__device__ __forceinline__ void ldsm4t(uint32_t a, uint32_t* r) {
    asm volatile("ldmatrix.sync.aligned.m8n8.x4.trans.shared.b16 {%0,%1,%2,%3}, [%4];"
                 : "=r"(r[0]), "=r"(r[1]), "=r"(r[2]), "=r"(r[3]) : "r"(a));
}
__device__ __forceinline__ void mma16816(float* c, const uint32_t* a, uint32_t b0, uint32_t b1) {
    asm volatile("mma.sync.aligned.m16n8k16.row.col.f32.bf16.bf16.f32 "
                 "{%0,%1,%2,%3}, {%4,%5,%6,%7}, {%8,%9}, {%0,%1,%2,%3};"
                 : "+f"(c[0]), "+f"(c[1]), "+f"(c[2]), "+f"(c[3])
                 : "r"(a[0]), "r"(a[1]), "r"(a[2]), "r"(a[3]), "r"(b0), "r"(b1));
}
// ILP-friendly split (independent cvts; ptxas schedules freely). Used in kernA.
__device__ __forceinline__ void split2a(float x0, float x1, uint32_t& hi, uint32_t& lo) {
    __nv_bfloat16 h0 = __float2bfloat16_rn(x0), h1 = __float2bfloat16_rn(x1);
    __nv_bfloat16 l0 = __float2bfloat16_rn(x0 - __bfloat162float(h0));
    __nv_bfloat16 l1 = __float2bfloat16_rn(x1 - __bfloat162float(h1));
    hi = ((uint32_t)__bfloat16_as_ushort(h1) << 16) | (uint32_t)__bfloat16_as_ushort(h0);
    lo = ((uint32_t)__bfloat16_as_ushort(l1) << 16) | (uint32_t)__bfloat16_as_ushort(l0);
}
// Packed split (6 SASS ops). Used where conversion is latency-tolerant.
__device__ __forceinline__ void split2(float x0, float x1, uint32_t& hi, uint32_t& lo) {
    uint32_t h;
    asm("cvt.rn.bf16x2.f32 %0, %1, %2;" : "=r"(h) : "f"(x1), "f"(x0));
    float h0 = __uint_as_float(h << 16);
    float h1 = __uint_as_float(h & 0xffff0000u);
    uint32_t l;
    float r0 = x0 - h0, r1 = x1 - h1;
    asm("cvt.rn.bf16x2.f32 %0, %1, %2;" : "=r"(l) : "f"(r1), "f"(r0));
    hi = h; lo = l;
}

// C(32x32 warp tile) += [Ah|Ah|Al] x [Bh|Bl|Bh] over kb_end 16-wide k-blocks.
template <bool TA, bool TB, int PA, int PB, bool FULLK>
__device__ __forceinline__ void gemm_tile(uint32_t AH, uint32_t AL, uint32_t BH, uint32_t BL,
                                          float (&acc)[2][4][4], int lane, int m0, int n0,
                                          int kb_end) {
    const uint32_t a_lane = TA
        ? (uint32_t)(((lane & 7) + ((lane >> 4) << 3)) * PA + (((lane >> 3) & 1) << 4))
        : (uint32_t)((lane & 15) * PA + ((lane >> 4) << 4));
    const uint32_t b_lane = TB
        ? (uint32_t)(((lane & 7) + (((lane >> 3) & 1) << 3)) * PB + (((lane >> 4) & 1) << 4))
        : (uint32_t)(((lane & 7) + ((lane & 16) >> 1)) * PB + ((lane & 8) << 1));
    const uint32_t aH = AH + a_lane + (TA ? (uint32_t)m0 * 2 : (uint32_t)m0 * PA);
    const uint32_t aL = AL + a_lane + (TA ? (uint32_t)m0 * 2 : (uint32_t)m0 * PA);
    const uint32_t bH = BH + b_lane + (TB ? (uint32_t)n0 * 2 : (uint32_t)n0 * PB);
    const uint32_t bL = BL + b_lane + (TB ? (uint32_t)n0 * 2 : (uint32_t)n0 * PB);
    const uint32_t a_kb = TA ? 16 * PA : 32;
    const uint32_t a_mf = TA ? 32 : 16 * PA;
    const uint32_t b_kb = TB ? 16 * PB : 32;
    const uint32_t b_nh = TB ? 32 : 16 * PB;
#pragma unroll
    for (int kb = 0; kb < 8; ++kb) {
        if (!FULLK && kb >= kb_end) break;
        uint32_t ah[2][4], al[2][4], bh[2][4], bl[2][4];
#pragma unroll
        for (int mf = 0; mf < 2; ++mf) {
            if (TA) { ldsm4t(aH + kb * a_kb + mf * a_mf, ah[mf]); ldsm4t(aL + kb * a_kb + mf * a_mf, al[mf]); }
            else    { ldsm4 (aH + kb * a_kb + mf * a_mf, ah[mf]); ldsm4 (aL + kb * a_kb + mf * a_mf, al[mf]); }
        }
#pragma unroll
        for (int nh = 0; nh < 2; ++nh) {
            if (TB) { ldsm4t(bH + kb * b_kb + nh * b_nh, bh[nh]); ldsm4t(bL + kb * b_kb + nh * b_nh, bl[nh]); }
            else    { ldsm4 (bH + kb * b_kb + nh * b_nh, bh[nh]); ldsm4 (bL + kb * b_kb + nh * b_nh, bl[nh]); }
        }
        // Term-outer: consecutive mmas never share an accumulator.
#pragma unroll
        for (int mf = 0; mf < 2; ++mf)
#pragma unroll
            for (int nf = 0; nf < 4; ++nf)
                mma16816(acc[mf][nf], ah[mf], bh[nf >> 1][(nf & 1) * 2], bh[nf >> 1][(nf & 1) * 2 + 1]);
#pragma unroll
        for (int mf = 0; mf < 2; ++mf)
#pragma unroll
            for (int nf = 0; nf < 4; ++nf)
                mma16816(acc[mf][nf], ah[mf], bl[nf >> 1][(nf & 1) * 2], bl[nf >> 1][(nf & 1) * 2 + 1]);
#pragma unroll
        for (int mf = 0; mf < 2; ++mf)
#pragma unroll
            for (int nf = 0; nf < 4; ++nf)
                mma16816(acc[mf][nf], al[mf], bh[nf >> 1][(nf & 1) * 2], bh[nf >> 1][(nf & 1) * 2 + 1]);
    }
}

// ---------------------------------------------------------------------------
// kernA: M_g = K_g^T V_g, two 64-col halves of V/M; 2 CTAs/SM, 256 threads.
// (Best-measured form: split2a, unbatched convert loops.)
// Chunk 15 of each (b,h) never consumed -> early exit.
// smem: KH 0, KL 34816, VhH 69632 (18432), VhL 88064. Total 106496.
// ---------------------------------------------------------------------------
#define A_SMEM 106496
__global__ void __launch_bounds__(256, 2) kernA(const float* __restrict__ k,
                                                const float* __restrict__ v) {
    const int g = blockIdx.x;
    if ((g & 15) == 15) return;          // M_15 unused (exclusive prefix)

    extern __shared__ char sm[];
    const uint32_t sb = smem_u32(sm);
    const int tid = threadIdx.x, lane = tid & 31, wid = tid >> 5;
    const float* kp = k + (size_t)g * CE;
    const float* vp = v + (size_t)g * CE;

#pragma unroll
    for (int it = 0; it < 16; ++it) {
        int idx4 = it * 256 + tid, t = idx4 >> 5, c4 = (idx4 & 31) << 2;
        float4 a = *(const float4*)(kp + (size_t)t * 128 + c4);
        uint32_t h01, l01, h23, l23;
        split2a(a.x, a.y, h01, l01); split2a(a.z, a.w, h23, l23);
        *(uint2*)(sm + t * IMRB + c4 * 2)         = make_uint2(h01, h23);
        *(uint2*)(sm + 34816 + t * IMRB + c4 * 2) = make_uint2(l01, l23);
    }

    const int m0 = (wid & 3) * 32, n0 = (wid >> 2) * 32;
    float* mp = g_M + (size_t)g * CE;

#pragma unroll 1
    for (int h = 0; h < 2; ++h) {
#pragma unroll
        for (int it = 0; it < 8; ++it) {
            int idx4 = it * 256 + tid, t = idx4 >> 4, c4 = (idx4 & 15) << 2;
            float4 b = *(const float4*)(vp + (size_t)t * 128 + h * 64 + c4);
            uint32_t h01, l01, h23, l23;
            split2a(b.x, b.y, h01, l01); split2a(b.z, b.w, h23, l23);
            *(uint2*)(sm + 69632 + t * HPRB + c4 * 2) = make_uint2(h01, h23);
            *(uint2*)(sm + 88064 + t * HPRB + c4 * 2) = make_uint2(l01, l23);
        }
        __syncthreads();

        float acc[2][4][4] = {};
        gemm_tile<true, true, IMRB, HPRB, true>(sb + 0, sb + 34816, sb + 69632, sb + 88064,
                                                acc, lane, m0, n0, 8);
#pragma unroll
        for (int mf = 0; mf < 2; ++mf)
#pragma unroll
            for (int nf = 0; nf < 4; ++nf) {
                int r = m0 + mf * 16 + (lane >> 2), c = h * 64 + n0 + nf * 8 + (lane & 3) * 2;
                *(float2*)(mp + (size_t)r * 128 + c)       = make_float2(acc[mf][nf][0], acc[mf][nf][1]);
                *(float2*)(mp + (size_t)(r + 8) * 128 + c) = make_float2(acc[mf][nf][2], acc[mf][nf][3]);
            }
        __syncthreads();
    }
}

// ---------------------------------------------------------------------------
// kernB: exclusive prefix over chunk states per (b,h). Streaming: no smem,
// no syncs; coalesced LDG.64 / STG.32. Grid 512 = 64 bh x 8 row-slices.
// ---------------------------------------------------------------------------
__global__ void __launch_bounds__(256, 1) kernB() {
    const int tid = threadIdx.x;
    const int bh = blockIdx.x >> 3, eb = blockIdx.x & 7;
    const size_t base = (size_t)bh * 16;

    int dl[4], e2[4];
#pragma unroll
    for (int u = 0; u < 4; ++u) {
        int idx = u * 256 + tid;
        dl[u] = idx >> 6;
        e2[u] = (idx & 63) * 2;
    }

    float run[8], cur[8], nxt[8];
#pragma unroll
    for (int u = 0; u < 8; ++u) run[u] = 0.f;

    {
        const float* M0 = g_M + base * CE;
#pragma unroll
        for (int u = 0; u < 4; ++u) {
            float2 x = *(const float2*)(M0 + (size_t)(eb * 16 + dl[u]) * 128 + e2[u]);
            cur[2 * u] = x.x; cur[2 * u + 1] = x.y;
        }
    }

    for (int c = 1; c < 16; ++c) {
        if (c <= 14) {
            const float* Mn = g_M + (base + c) * CE;
#pragma unroll
            for (int u = 0; u < 4; ++u) {
                float2 x = *(const float2*)(Mn + (size_t)(eb * 16 + dl[u]) * 128 + e2[u]);
                nxt[2 * u] = x.x; nxt[2 * u + 1] = x.y;
            }
        }
#pragma unroll
        for (int u = 0; u < 8; ++u) run[u] += cur[u];

        char* ph = (char*)(g_SH + (base + c) * IMU4) + eb * 4352;
        char* pl = (char*)(g_SL + (base + c) * IMU4) + eb * 4352;
#pragma unroll
        for (int u = 0; u < 4; ++u) {
            uint32_t h, l;
            split2(run[2 * u], run[2 * u + 1], h, l);
            int off = dl[u] * IMRB + e2[u] * 2;
            *(uint32_t*)(ph + off) = h;
            *(uint32_t*)(pl + off) = l;
        }
#pragma unroll
        for (int u = 0; u < 8; ++u) cur[u] = nxt[u];
    }
}

// ---------------------------------------------------------------------------
// kernC: O = Q@S + (tril ⊙ QK^T)@V. 512 threads, 16 warps, 1 CTA/SM.
// Phase order: [S cp.async + Q/K convert] -> P GEMM (S flying) ->
// [V cp.async into dead K region] -> O1 GEMM (V flying) ->
// split P (regs) + convert V -> O2. Warp->tile LUT balances SMSP kb-loads
// to {72,72,70,74} (Latin square gave {76,68,76,68}).
// smem: QH 0 (->P), QL 34816, KH 69632 (->V fp32 staging), KL 104448,
//       SH 139264 (->V imgs), SL 174080. Total 208896.
// ---------------------------------------------------------------------------
#define C_SMEM 208896
__global__ void __launch_bounds__(512, 1) kernC(const float* __restrict__ q,
                                                const float* __restrict__ k,
                                                const float* __restrict__ v,
                                                float* __restrict__ out) {
    extern __shared__ char sm[];
    const uint32_t sb = smem_u32(sm);
    const int tid = threadIdx.x, lane = tid & 31, wid = tid >> 5;
    const int g = blockIdx.x;
    const bool hasS = (g & 15) != 0;
    const float* qp = q + (size_t)g * CE;
    const float* kp = k + (size_t)g * CE;
    const float* vp = v + (size_t)g * CE;

    // Phase 1: S images cp.async (hides under convert + P GEMM).
    if (hasS) {
        const uint4* shh = g_SH + (size_t)g * IMU4;
        const uint4* sll = g_SL + (size_t)g * IMU4;
        for (int i = tid; i < IMU4; i += 512) {
            uint32_t d0 = sb + 139264 + i * 16, d1 = sb + 174080 + i * 16;
            asm volatile("cp.async.cg.shared.global [%0], [%1], 16;" :: "r"(d0), "l"(shh + i) : "memory");
            asm volatile("cp.async.cg.shared.global [%0], [%1], 16;" :: "r"(d1), "l"(sll + i) : "memory");
        }
        asm volatile("cp.async.commit_group;" ::: "memory");
    }
    // Convert Q, K; batched pairs (4 LDG.128 in flight).
#pragma unroll
    for (int it = 0; it < 8; it += 2) {
        int idxA = it * 512 + tid, iA = idxA >> 5, cA = (idxA & 31) << 2;
        int idxB = (it + 1) * 512 + tid, iB = idxB >> 5, cB = (idxB & 31) << 2;
        float4 a0 = *(const float4*)(qp + (size_t)iA * 128 + cA);
        float4 b0 = *(const float4*)(kp + (size_t)iA * 128 + cA);
        float4 a1 = *(const float4*)(qp + (size_t)iB * 128 + cB);
        float4 b1 = *(const float4*)(kp + (size_t)iB * 128 + cB);
        uint32_t h01, l01, h23, l23;
        split2(a0.x, a0.y, h01, l01); split2(a0.z, a0.w, h23, l23);
        *(uint2*)(sm + iA * IMRB + cA * 2)         = make_uint2(h01, h23);
        *(uint2*)(sm + 34816 + iA * IMRB + cA * 2) = make_uint2(l01, l23);
        split2(b0.x, b0.y, h01, l01); split2(b0.z, b0.w, h23, l23);
        *(uint2*)(sm + 69632 + iA * IMRB + cA * 2)  = make_uint2(h01, h23);
        *(uint2*)(sm + 104448 + iA * IMRB + cA * 2) = make_uint2(l01, l23);
        split2(a1.x, a1.y, h01, l01); split2(a1.z, a1.w, h23, l23);
        *(uint2*)(sm + iB * IMRB + cB * 2)         = make_uint2(h01, h23);
        *(uint2*)(sm + 34816 + iB * IMRB + cB * 2) = make_uint2(l01, l23);
        split2(b1.x, b1.y, h01, l01); split2(b1.z, b1.w, h23, l23);
        *(uint2*)(sm + 69632 + iB * IMRB + cB * 2)  = make_uint2(h01, h23);
        *(uint2*)(sm + 104448 + iB * IMRB + cB * 2) = make_uint2(l01, l23);
    }
    __syncthreads();     // Q, K images ready (S NOT waited — P doesn't need it)

    // SMSP-balanced warp->tile LUT (2-bit fields indexed by wid).
    const int mi = (int)((0x0152B6BFu >> (2 * wid)) & 3u);
    const int ni = (int)((0xE673B064u >> (2 * wid)) & 3u);
    const int m0 = mi * 32, n0 = ni * 32;

    // Phase 2: P = Q K^T (both natural). Upper-triangle tiles all-zero -> skip.
    float acc1[2][4][4] = {};
    if (ni <= mi)
        gemm_tile<false, false, IMRB, IMRB, true>(sb + 0, sb + 34816, sb + 69632, sb + 104448,
                                                  acc1, lane, m0, n0, 8);
    __syncthreads();     // all P reads done; K region dead

    // Phase 3: prefetch raw fp32 V (64 KB) into the K region; flies under O1.
    {
        const uint4* vp4 = (const uint4*)vp;
        for (int i = tid; i < 4096; i += 512) {
            uint32_t d0 = sb + 69632 + i * 16;
            asm volatile("cp.async.cg.shared.global [%0], [%1], 16;" :: "r"(d0), "l"(vp4 + i) : "memory");
        }
        asm volatile("cp.async.commit_group;" ::: "memory");
    }
    // Ensure S landed (allow V group to stay in flight), make visible CTA-wide.
    asm volatile("cp.async.wait_group 1;" ::: "memory");
    __syncthreads();

    // Phase 4: O1 = Q @ S (S natural -> trans B). Chunk 0: S=0, skip.
    float acc2[2][4][4] = {};
    if (hasS)
        gemm_tile<false, true, IMRB, IMRB, true>(sb + 0, sb + 34816, sb + 139264, sb + 174080,
                                                 acc2, lane, m0, n0, 8);
    asm volatile("cp.async.wait_group 0;" ::: "memory");
    __syncthreads();     // Q, S regions dead; V fp32 landed in K region

    // Phase 5: mask + split P (from regs) into Q region; convert V (K region
    // fp32) into S region images.
    if (ni <= mi) {
#pragma unroll
        for (int mf = 0; mf < 2; ++mf)
#pragma unroll
            for (int nf = 0; nf < 4; ++nf) {
                int r = m0 + mf * 16 + (lane >> 2), c = n0 + nf * 8 + (lane & 3) * 2;
                float c0 = (c <= r) ? acc1[mf][nf][0] : 0.f;
                float c1 = (c + 1 <= r) ? acc1[mf][nf][1] : 0.f;
                float c2 = (c <= r + 8) ? acc1[mf][nf][2] : 0.f;
                float c3 = (c + 1 <= r + 8) ? acc1[mf][nf][3] : 0.f;
                uint32_t h, l;
                split2(c0, c1, h, l);
                *(uint32_t*)(sm + r * IMRB + c * 2)         = h;
                *(uint32_t*)(sm + 34816 + r * IMRB + c * 2) = l;
                split2(c2, c3, h, l);
                *(uint32_t*)(sm + (r + 8) * IMRB + c * 2)         = h;
                *(uint32_t*)(sm + 34816 + (r + 8) * IMRB + c * 2) = l;
            }
    }
    {
        const float* vf = (const float*)(sm + 69632);
#pragma unroll
        for (int it = 0; it < 8; ++it) {
            int idx4 = it * 512 + tid, t = idx4 >> 5, c4 = (idx4 & 31) << 2;
            float4 b = *(const float4*)(vf + idx4 * 4);
            uint32_t h01, l01, h23, l23;
            split2(b.x, b.y, h01, l01); split2(b.z, b.w, h23, l23);
            *(uint2*)(sm + 139264 + t * IMRB + c4 * 2) = make_uint2(h01, h23);
            *(uint2*)(sm + 174080 + t * IMRB + c4 * 2) = make_uint2(l01, l23);
        }
    }
    __syncthreads();

    // Phase 6: O2: acc2 += P @ V (P images in Q region; V images in S region),
    // k truncated to the nonzero column range of this row block.
    gemm_tile<false, true, IMRB, IMRB, false>(sb + 0, sb + 34816, sb + 139264, sb + 174080,
                                              acc2, lane, m0, n0, 2 * mi + 2);

    float* op = out + (size_t)g * CE;
#pragma unroll
    for (int mf = 0; mf < 2; ++mf)
#pragma unroll
        for (int nf = 0; nf < 4; ++nf) {
            int r = m0 + mf * 16 + (lane >> 2), c = n0 + nf * 8 + (lane & 3) * 2;
            *(float2*)(op + (size_t)r * 128 + c)       = make_float2(acc2[mf][nf][0], acc2[mf][nf][1]);
            *(float2*)(op + (size_t)(r + 8) * 128 + c) = make_float2(acc2[mf][nf][2], acc2[mf][nf][3]);
        }
}

// ---------------------------------------------------------------------------

extern "C" void kernel_launch(void* const* d_in, const int* in_sizes, int n_in,
                              void* d_out, int out_size) {
    const float* q = (const float*)d_in[0];
    const float* k = (const float*)d_in[1];
    const float* v = (const float*)d_in[2];
    float* out = (float*)d_out;

    cudaFuncSetAttribute(kernA, cudaFuncAttributeMaxDynamicSharedMemorySize, A_SMEM);
    cudaFuncSetAttribute(kernC, cudaFuncAttributeMaxDynamicSharedMemorySize, C_SMEM);

    kernA<<<NCHUNK, 256, A_SMEM>>>(k, v);
    kernB<<<512, 256>>>();
    kernC<<<NCHUNK, 512, C_SMEM>>>(q, k, v, out);
}

// round 17
// speedup vs baseline: 1.0101x; 1.0101x over previous
#include <cuda_runtime.h>
#include <cuda_bf16.h>
#include <stdint.h>

// Linear causal attention, chunked states, bf16-split mma.sync.
//   O_c = Q_c @ S_c + (tril ⊙ Q_c K_c^T) @ V_c,  S_c = sum_{c'<c} K_{c'}^T V_{c'}
// fp32 GEMM = Ah*Bh + Ah*Bl + Al*Bh in bf16, fp32 accum. Operands natural [t][d];
// transposed fragments via ldmatrix.trans. Causal structure exploited at tile,
// k-loop, and (new) sub-tile granularity: diagonal P tiles skip their two
// fully-above-diagonal m16n8 fragments.

#define NCHUNK 1024
#define CE     16384
#define IMRB   272             // bytes per full image row (136 bf16)
#define IMU4   2176            // uint4 per 128-row full image
#define HPRB   144             // bytes per half image row (72 bf16)

__device__ float g_M[(size_t)NCHUNK * CE];        // K^T V per chunk, fp32
__device__ uint4 g_SH[(size_t)NCHUNK * IMU4];     // exclusive-prefix S, split images
__device__ uint4 g_SL[(size_t)NCHUNK * IMU4];

// ---------------- helpers ----------------
__device__ __forceinline__ uint32_t smem_u32(const void* p) {
    uint32_t a;
    asm("{ .reg .u64 t; cvta.to.shared.u64 t, %1; cvt.u32.u64 %0, t; }" : "=r"(a) : "l"(p));
    return a;
}
__device__ __forceinline__ void ldsm4(uint32_t a, uint32_t* r) {
    asm volatile("ldmatrix.sync.aligned.m8n8.x4.shared.b16 {%0,%1,%2,%3}, [%4];"
                 : "=r"(r[0]), "=r"(r[1]), "=r"(r[2]), "=r"(r[3]) : "r"(a));
}
__device__ __forceinline__ void ldsm4t(uint32_t a, uint32_t* r) {
    asm volatile("ldmatrix.sync.aligned.m8n8.x4.trans.shared.b16 {%0,%1,%2,%3}, [%4];"
                 : "=r"(r[0]), "=r"(r[1]), "=r"(r[2]), "=r"(r[3]) : "r"(a));
}
__device__ __forceinline__ void mma16816(float* c, const uint32_t* a, uint32_t b0, uint32_t b1) {
    asm volatile("mma.sync.aligned.m16n8k16.row.col.f32.bf16.bf16.f32 "
                 "{%0,%1,%2,%3}, {%4,%5,%6,%7}, {%8,%9}, {%0,%1,%2,%3};"
                 : "+f"(c[0]), "+f"(c[1]), "+f"(c[2]), "+f"(c[3])
                 : "r"(a[0]), "r"(a[1]), "r"(a[2]), "r"(a[3]), "r"(b0), "r"(b1));
}
// ILP-friendly split (independent cvts; ptxas schedules freely). Used in kernA.
__device__ __forceinline__ void split2a(float x0, float x1, uint32_t& hi, uint32_t& lo) {
    __nv_bfloat16 h0 = __float2bfloat16_rn(x0), h1 = __float2bfloat16_rn(x1);
    __nv_bfloat16 l0 = __float2bfloat16_rn(x0 - __bfloat162float(h0));
    __nv_bfloat16 l1 = __float2bfloat16_rn(x1 - __bfloat162float(h1));
    hi = ((uint32_t)__bfloat16_as_ushort(h1) << 16) | (uint32_t)__bfloat16_as_ushort(h0);
    lo = ((uint32_t)__bfloat16_as_ushort(l1) << 16) | (uint32_t)__bfloat16_as_ushort(l0);
}
// Packed split (6 SASS ops). Used where conversion is latency-tolerant.
__device__ __forceinline__ void split2(float x0, float x1, uint32_t& hi, uint32_t& lo) {
    uint32_t h;
    asm("cvt.rn.bf16x2.f32 %0, %1, %2;" : "=r"(h) : "f"(x1), "f"(x0));
    float h0 = __uint_as_float(h << 16);
    float h1 = __uint_as_float(h & 0xffff0000u);
    uint32_t l;
    float r0 = x0 - h0, r1 = x1 - h1;
    asm("cvt.rn.bf16x2.f32 %0, %1, %2;" : "=r"(l) : "f"(r1), "f"(r0));
    hi = h; lo = l;
}

// C(32x32 warp tile) += [Ah|Ah|Al] x [Bh|Bl|Bh] over kb_end 16-wide k-blocks.
// DIAG: warp tile sits on the causal diagonal (m0==n0) -> sub-tiles
// (mf=0, nf>=2) are entirely above the diagonal (later masked to 0) -> skip.
template <bool TA, bool TB, int PA, int PB, bool FULLK, bool DIAG = false>
__device__ __forceinline__ void gemm_tile(uint32_t AH, uint32_t AL, uint32_t BH, uint32_t BL,
                                          float (&acc)[2][4][4], int lane, int m0, int n0,
                                          int kb_end) {
    const uint32_t a_lane = TA
        ? (uint32_t)(((lane & 7) + ((lane >> 4) << 3)) * PA + (((lane >> 3) & 1) << 4))
        : (uint32_t)((lane & 15) * PA + ((lane >> 4) << 4));
    const uint32_t b_lane = TB
        ? (uint32_t)(((lane & 7) + (((lane >> 3) & 1) << 3)) * PB + (((lane >> 4) & 1) << 4))
        : (uint32_t)(((lane & 7) + ((lane & 16) >> 1)) * PB + ((lane & 8) << 1));
    const uint32_t aH = AH + a_lane + (TA ? (uint32_t)m0 * 2 : (uint32_t)m0 * PA);
    const uint32_t aL = AL + a_lane + (TA ? (uint32_t)m0 * 2 : (uint32_t)m0 * PA);
    const uint32_t bH = BH + b_lane + (TB ? (uint32_t)n0 * 2 : (uint32_t)n0 * PB);
    const uint32_t bL = BL + b_lane + (TB ? (uint32_t)n0 * 2 : (uint32_t)n0 * PB);
    const uint32_t a_kb = TA ? 16 * PA : 32;
    const uint32_t a_mf = TA ? 32 : 16 * PA;
    const uint32_t b_kb = TB ? 16 * PB : 32;
    const uint32_t b_nh = TB ? 32 : 16 * PB;
#pragma unroll
    for (int kb = 0; kb < 8; ++kb) {
        if (!FULLK && kb >= kb_end) break;
        uint32_t ah[2][4], al[2][4], bh[2][4], bl[2][4];
#pragma unroll
        for (int mf = 0; mf < 2; ++mf) {
            if (TA) { ldsm4t(aH + kb * a_kb + mf * a_mf, ah[mf]); ldsm4t(aL + kb * a_kb + mf * a_mf, al[mf]); }
            else    { ldsm4 (aH + kb * a_kb + mf * a_mf, ah[mf]); ldsm4 (aL + kb * a_kb + mf * a_mf, al[mf]); }
        }
#pragma unroll
        for (int nh = 0; nh < 2; ++nh) {
            if (TB) { ldsm4t(bH + kb * b_kb + nh * b_nh, bh[nh]); ldsm4t(bL + kb * b_kb + nh * b_nh, bl[nh]); }
            else    { ldsm4 (bH + kb * b_kb + nh * b_nh, bh[nh]); ldsm4 (bL + kb * b_kb + nh * b_nh, bl[nh]); }
        }
        // Term-outer: consecutive mmas never share an accumulator.
#pragma unroll
        for (int mf = 0; mf < 2; ++mf)
#pragma unroll
            for (int nf = 0; nf < 4; ++nf) {
                if (DIAG && mf == 0 && nf >= 2) continue;   // above diagonal
                mma16816(acc[mf][nf], ah[mf], bh[nf >> 1][(nf & 1) * 2], bh[nf >> 1][(nf & 1) * 2 + 1]);
            }
#pragma unroll
        for (int mf = 0; mf < 2; ++mf)
#pragma unroll
            for (int nf = 0; nf < 4; ++nf) {
                if (DIAG && mf == 0 && nf >= 2) continue;
                mma16816(acc[mf][nf], ah[mf], bl[nf >> 1][(nf & 1) * 2], bl[nf >> 1][(nf & 1) * 2 + 1]);
            }
#pragma unroll
        for (int mf = 0; mf < 2; ++mf)
#pragma unroll
            for (int nf = 0; nf < 4; ++nf) {
                if (DIAG && mf == 0 && nf >= 2) continue;
                mma16816(acc[mf][nf], al[mf], bh[nf >> 1][(nf & 1) * 2], bh[nf >> 1][(nf & 1) * 2 + 1]);
            }
    }
}

// ---------------------------------------------------------------------------
// kernA: M_g = K_g^T V_g, two 64-col halves of V/M; 2 CTAs/SM, 256 threads.
// (Best-measured form: split2a, unbatched convert loops.)
// Chunk 15 of each (b,h) never consumed -> early exit.
// smem: KH 0, KL 34816, VhH 69632 (18432), VhL 88064. Total 106496.
// ---------------------------------------------------------------------------
#define A_SMEM 106496
__global__ void __launch_bounds__(256, 2) kernA(const float* __restrict__ k,
                                                const float* __restrict__ v) {
    const int g = blockIdx.x;
    if ((g & 15) == 15) return;          // M_15 unused (exclusive prefix)

    extern __shared__ char sm[];
    const uint32_t sb = smem_u32(sm);
    const int tid = threadIdx.x, lane = tid & 31, wid = tid >> 5;
    const float* kp = k + (size_t)g * CE;
    const float* vp = v + (size_t)g * CE;

#pragma unroll
    for (int it = 0; it < 16; ++it) {
        int idx4 = it * 256 + tid, t = idx4 >> 5, c4 = (idx4 & 31) << 2;
        float4 a = *(const float4*)(kp + (size_t)t * 128 + c4);
        uint32_t h01, l01, h23, l23;
        split2a(a.x, a.y, h01, l01); split2a(a.z, a.w, h23, l23);
        *(uint2*)(sm + t * IMRB + c4 * 2)         = make_uint2(h01, h23);
        *(uint2*)(sm + 34816 + t * IMRB + c4 * 2) = make_uint2(l01, l23);
    }

    const int m0 = (wid & 3) * 32, n0 = (wid >> 2) * 32;
    float* mp = g_M + (size_t)g * CE;

#pragma unroll 1
    for (int h = 0; h < 2; ++h) {
#pragma unroll
        for (int it = 0; it < 8; ++it) {
            int idx4 = it * 256 + tid, t = idx4 >> 4, c4 = (idx4 & 15) << 2;
            float4 b = *(const float4*)(vp + (size_t)t * 128 + h * 64 + c4);
            uint32_t h01, l01, h23, l23;
            split2a(b.x, b.y, h01, l01); split2a(b.z, b.w, h23, l23);
            *(uint2*)(sm + 69632 + t * HPRB + c4 * 2) = make_uint2(h01, h23);
            *(uint2*)(sm + 88064 + t * HPRB + c4 * 2) = make_uint2(l01, l23);
        }
        __syncthreads();

        float acc[2][4][4] = {};
        gemm_tile<true, true, IMRB, HPRB, true>(sb + 0, sb + 34816, sb + 69632, sb + 88064,
                                                acc, lane, m0, n0, 8);
#pragma unroll
        for (int mf = 0; mf < 2; ++mf)
#pragma unroll
            for (int nf = 0; nf < 4; ++nf) {
                int r = m0 + mf * 16 + (lane >> 2), c = h * 64 + n0 + nf * 8 + (lane & 3) * 2;
                *(float2*)(mp + (size_t)r * 128 + c)       = make_float2(acc[mf][nf][0], acc[mf][nf][1]);
                *(float2*)(mp + (size_t)(r + 8) * 128 + c) = make_float2(acc[mf][nf][2], acc[mf][nf][3]);
            }
        __syncthreads();
    }
}

// ---------------------------------------------------------------------------
// kernB: exclusive prefix over chunk states per (b,h). Streaming: no smem,
// no syncs; coalesced LDG.64 / STG.32. Grid 512 = 64 bh x 8 row-slices.
// ---------------------------------------------------------------------------
__global__ void __launch_bounds__(256, 1) kernB() {
    const int tid = threadIdx.x;
    const int bh = blockIdx.x >> 3, eb = blockIdx.x & 7;
    const size_t base = (size_t)bh * 16;

    int dl[4], e2[4];
#pragma unroll
    for (int u = 0; u < 4; ++u) {
        int idx = u * 256 + tid;
        dl[u] = idx >> 6;
        e2[u] = (idx & 63) * 2;
    }

    float run[8], cur[8], nxt[8];
#pragma unroll
    for (int u = 0; u < 8; ++u) run[u] = 0.f;

    {
        const float* M0 = g_M + base * CE;
#pragma unroll
        for (int u = 0; u < 4; ++u) {
            float2 x = *(const float2*)(M0 + (size_t)(eb * 16 + dl[u]) * 128 + e2[u]);
            cur[2 * u] = x.x; cur[2 * u + 1] = x.y;
        }
    }

    for (int c = 1; c < 16; ++c) {
        if (c <= 14) {
            const float* Mn = g_M + (base + c) * CE;
#pragma unroll
            for (int u = 0; u < 4; ++u) {
                float2 x = *(const float2*)(Mn + (size_t)(eb * 16 + dl[u]) * 128 + e2[u]);
                nxt[2 * u] = x.x; nxt[2 * u + 1] = x.y;
            }
        }
#pragma unroll
        for (int u = 0; u < 8; ++u) run[u] += cur[u];

        char* ph = (char*)(g_SH + (base + c) * IMU4) + eb * 4352;
        char* pl = (char*)(g_SL + (base + c) * IMU4) + eb * 4352;
#pragma unroll
        for (int u = 0; u < 4; ++u) {
            uint32_t h, l;
            split2(run[2 * u], run[2 * u + 1], h, l);
            int off = dl[u] * IMRB + e2[u] * 2;
            *(uint32_t*)(ph + off) = h;
            *(uint32_t*)(pl + off) = l;
        }
#pragma unroll
        for (int u = 0; u < 8; ++u) cur[u] = nxt[u];
    }
}

// ---------------------------------------------------------------------------
// kernC: O = Q@S + (tril ⊙ QK^T)@V. 512 threads, 16 warps, 1 CTA/SM.
// Warp tile map: mi = wid>>2, ni = (wid - mi) & 3 (SMSP-balanced Latin square).
// P chain skipped for ni>mi, diagonal tiles skip above-diagonal sub-frags;
// O2 k-loop truncated to kb < 2*mi+2. Chunk 0: S=0 -> skip S load and O1.
// smem: QH 0 (->P), QL 34816, KH 69632 (->V imgs), KL 104448,
//       SH 139264 (->V fp32 staging), SL 174080. Total 208896.
// ---------------------------------------------------------------------------
#define C_SMEM 208896
__global__ void __launch_bounds__(512, 1) kernC(const float* __restrict__ q,
                                                const float* __restrict__ k,
                                                const float* __restrict__ v,
                                                float* __restrict__ out) {
    extern __shared__ char sm[];
    const uint32_t sb = smem_u32(sm);
    const int tid = threadIdx.x, lane = tid & 31, wid = tid >> 5;
    const int g = blockIdx.x;
    const bool hasS = (g & 15) != 0;
    const float* qp = q + (size_t)g * CE;
    const float* kp = k + (size_t)g * CE;
    const float* vp = v + (size_t)g * CE;

    // Async S images overlap the Q/K conversion (skipped for chunk 0: S=0).
    if (hasS) {
        const uint4* shh = g_SH + (size_t)g * IMU4;
        const uint4* sll = g_SL + (size_t)g * IMU4;
        for (int i = tid; i < IMU4; i += 512) {
            uint32_t d0 = sb + 139264 + i * 16, d1 = sb + 174080 + i * 16;
            asm volatile("cp.async.cg.shared.global [%0], [%1], 16;" :: "r"(d0), "l"(shh + i) : "memory");
            asm volatile("cp.async.cg.shared.global [%0], [%1], 16;" :: "r"(d1), "l"(sll + i) : "memory");
        }
        asm volatile("cp.async.commit_group;" ::: "memory");
    }
    // Convert Q, K; batched pairs (4 LDG.128 in flight).
#pragma unroll
    for (int it = 0; it < 8; it += 2) {
        int idxA = it * 512 + tid, iA = idxA >> 5, cA = (idxA & 31) << 2;
        int idxB = (it + 1) * 512 + tid, iB = idxB >> 5, cB = (idxB & 31) << 2;
        float4 a0 = *(const float4*)(qp + (size_t)iA * 128 + cA);
        float4 b0 = *(const float4*)(kp + (size_t)iA * 128 + cA);
        float4 a1 = *(const float4*)(qp + (size_t)iB * 128 + cB);
        float4 b1 = *(const float4*)(kp + (size_t)iB * 128 + cB);
        uint32_t h01, l01, h23, l23;
        split2(a0.x, a0.y, h01, l01); split2(a0.z, a0.w, h23, l23);
        *(uint2*)(sm + iA * IMRB + cA * 2)         = make_uint2(h01, h23);
        *(uint2*)(sm + 34816 + iA * IMRB + cA * 2) = make_uint2(l01, l23);
        split2(b0.x, b0.y, h01, l01); split2(b0.z, b0.w, h23, l23);
        *(uint2*)(sm + 69632 + iA * IMRB + cA * 2)  = make_uint2(h01, h23);
        *(uint2*)(sm + 104448 + iA * IMRB + cA * 2) = make_uint2(l01, l23);
        split2(a1.x, a1.y, h01, l01); split2(a1.z, a1.w, h23, l23);
        *(uint2*)(sm + iB * IMRB + cB * 2)         = make_uint2(h01, h23);
        *(uint2*)(sm + 34816 + iB * IMRB + cB * 2) = make_uint2(l01, l23);
        split2(b1.x, b1.y, h01, l01); split2(b1.z, b1.w, h23, l23);
        *(uint2*)(sm + 69632 + iB * IMRB + cB * 2)  = make_uint2(h01, h23);
        *(uint2*)(sm + 104448 + iB * IMRB + cB * 2) = make_uint2(l01, l23);
    }
    if (hasS) asm volatile("cp.async.wait_group 0;" ::: "memory");
    __syncthreads();

    const int mi = wid >> 2, ni = (wid - mi) & 3;
    const int m0 = mi * 32, n0 = ni * 32;

    // O1 = Q @ S (S natural -> trans B). Chunk 0: S=0, skip.
    float acc2[2][4][4] = {};
    if (hasS)
        gemm_tile<false, true, IMRB, IMRB, true>(sb + 0, sb + 34816, sb + 139264, sb + 174080,
                                                 acc2, lane, m0, n0, 8);
    __syncthreads();     // S region dead

    // Prefetch raw fp32 V (64 KB) into the S region; flies under the P GEMM.
    {
        const uint4* vp4 = (const uint4*)vp;
        for (int i = tid; i < 4096; i += 512) {
            uint32_t d0 = sb + 139264 + i * 16;
            asm volatile("cp.async.cg.shared.global [%0], [%1], 16;" :: "r"(d0), "l"(vp4 + i) : "memory");
        }
        asm volatile("cp.async.commit_group;" ::: "memory");
    }

    // P = Q K^T (both natural). Upper-triangle tiles all-zero -> skipped;
    // diagonal tiles skip their above-diagonal sub-fragments.
    float acc1[2][4][4] = {};
    if (ni == mi)
        gemm_tile<false, false, IMRB, IMRB, true, true>(sb + 0, sb + 34816, sb + 69632, sb + 104448,
                                                        acc1, lane, m0, n0, 8);
    else if (ni < mi)
        gemm_tile<false, false, IMRB, IMRB, true>(sb + 0, sb + 34816, sb + 69632, sb + 104448,
                                                  acc1, lane, m0, n0, 8);
    asm volatile("cp.async.wait_group 0;" ::: "memory");
    __syncthreads();     // Q, K regions dead; V fp32 landed

    // Mask + split P into Q region; convert V (smem fp32) into K region images.
    if (ni <= mi) {
#pragma unroll
        for (int mf = 0; mf < 2; ++mf)
#pragma unroll
            for (int nf = 0; nf < 4; ++nf) {
                int r = m0 + mf * 16 + (lane >> 2), c = n0 + nf * 8 + (lane & 3) * 2;
                float c0 = (c <= r) ? acc1[mf][nf][0] : 0.f;
                float c1 = (c + 1 <= r) ? acc1[mf][nf][1] : 0.f;
                float c2 = (c <= r + 8) ? acc1[mf][nf][2] : 0.f;
                float c3 = (c + 1 <= r + 8) ? acc1[mf][nf][3] : 0.f;
                uint32_t h, l;
                split2(c0, c1, h, l);
                *(uint32_t*)(sm + r * IMRB + c * 2)         = h;
                *(uint32_t*)(sm + 34816 + r * IMRB + c * 2) = l;
                split2(c2, c3, h, l);
                *(uint32_t*)(sm + (r + 8) * IMRB + c * 2)         = h;
                *(uint32_t*)(sm + 34816 + (r + 8) * IMRB + c * 2) = l;
            }
    }
    {
        const float* vf = (const float*)(sm + 139264);
#pragma unroll
        for (int it = 0; it < 8; ++it) {
            int idx4 = it * 512 + tid, t = idx4 >> 5, c4 = (idx4 & 31) << 2;
            float4 b = *(const float4*)(vf + idx4 * 4);
            uint32_t h01, l01, h23, l23;
            split2(b.x, b.y, h01, l01); split2(b.z, b.w, h23, l23);
            *(uint2*)(sm + 69632 + t * IMRB + c4 * 2)  = make_uint2(h01, h23);
            *(uint2*)(sm + 104448 + t * IMRB + c4 * 2) = make_uint2(l01, l23);
        }
    }
    __syncthreads();

    // O2: acc2 += P @ V, k truncated to the nonzero column range of this row block.
    gemm_tile<false, true, IMRB, IMRB, false>(sb + 0, sb + 34816, sb + 69632, sb + 104448,
                                              acc2, lane, m0, n0, 2 * mi + 2);

    float* op = out + (size_t)g * CE;
#pragma unroll
    for (int mf = 0; mf < 2; ++mf)
#pragma unroll
        for (int nf = 0; nf < 4; ++nf) {
            int r = m0 + mf * 16 + (lane >> 2), c = n0 + nf * 8 + (lane & 3) * 2;
            *(float2*)(op + (size_t)r * 128 + c)       = make_float2(acc2[mf][nf][0], acc2[mf][nf][1]);
            *(float2*)(op + (size_t)(r + 8) * 128 + c) = make_float2(acc2[mf][nf][2], acc2[mf][nf][3]);
        }
}

// ---------------------------------------------------------------------------

extern "C" void kernel_launch(void* const* d_in, const int* in_sizes, int n_in,
                              void* d_out, int out_size) {
    const float* q = (const float*)d_in[0];
    const float* k = (const float*)d_in[1];
    const float* v = (const float*)d_in[2];
    float* out = (float*)d_out;

    cudaFuncSetAttribute(kernA, cudaFuncAttributeMaxDynamicSharedMemorySize, A_SMEM);
    cudaFuncSetAttribute(kernC, cudaFuncAttributeMaxDynamicSharedMemorySize, C_SMEM);

    kernA<<<NCHUNK, 256, A_SMEM>>>(k, v);
    kernB<<<512, 256>>>();
    kernC<<<NCHUNK, 512, C_SMEM>>>(q, k, v, out);
}